// round 2
// baseline (speedup 1.0000x reference)
#include <cuda_runtime.h>

#define BB 4096
#define DD 1024
#define THREADS 256
#define EPSF 1e-8f
#define MARGIN 0.2f
#define NACC 11

__global__ void init_out_kernel(float* out) {
    out[0] = 0.0f;
}

__device__ __forceinline__ void block_reduce_11(float* v, float* smem, int tid) {
    // warp-level reduction of 11 accumulators, then cross-warp via shared mem
    #pragma unroll
    for (int a = 0; a < NACC; a++) {
        float x = v[a];
        #pragma unroll
        for (int off = 16; off > 0; off >>= 1)
            x += __shfl_xor_sync(0xFFFFFFFFu, x, off);
        v[a] = x;
    }
    int warp = tid >> 5, lane = tid & 31;
    if (lane == 0) {
        #pragma unroll
        for (int a = 0; a < NACC; a++)
            smem[warp * NACC + a] = v[a];
    }
    __syncthreads();
    if (warp == 0) {
        #pragma unroll
        for (int a = 0; a < NACC; a++) {
            float x = (lane < (THREADS / 32)) ? smem[lane * NACC + a] : 0.0f;
            #pragma unroll
            for (int off = 4; off > 0; off >>= 1)
                x += __shfl_xor_sync(0xFFFFFFFFu, x, off);
            v[a] = x;
        }
    }
}

__global__ __launch_bounds__(THREADS)   // NO min-blocks clamp: allow ~56 regs so all 6
                                        // float4 loads stay in flight (MLP=6)
void contrastive_kernel(const float* __restrict__ img,
                        const float* __restrict__ txt,
                        const int* __restrict__ cand_img,
                        const int* __restrict__ cand_txt,
                        float* __restrict__ out) {
    const int b = blockIdx.x;
    const int tid = threadIdx.x;
    const int lane = tid & 31;

    // lane 0 of each warp loads the 4 candidate indices, broadcast via shfl
    int idx4 = 0;
    if (lane < 4) {
        const int* src = (lane < 2) ? cand_txt : cand_img;
        idx4 = src[2 * b + (lane & 1)];
    }
    const int ct0 = __shfl_sync(0xFFFFFFFFu, idx4, 0);
    const int ct1 = __shfl_sync(0xFFFFFFFFu, idx4, 1);
    const int ci0 = __shfl_sync(0xFFFFFFFFu, idx4, 2);
    const int ci1 = __shfl_sync(0xFFFFFFFFu, idx4, 3);

    const float4* ib  = (const float4*)(img + (size_t)b   * DD);
    const float4* tb  = (const float4*)(txt + (size_t)b   * DD);
    const float4* tc0 = (const float4*)(txt + (size_t)ct0 * DD);
    const float4* tc1 = (const float4*)(txt + (size_t)ct1 * DD);
    const float4* ic0 = (const float4*)(img + (size_t)ci0 * DD);
    const float4* ic1 = (const float4*)(img + (size_t)ci1 * DD);

    // one float4 per thread per row (DD/4 == THREADS); all 6 loads independent
    float4 vi  = ib[tid];
    float4 vt  = tb[tid];
    float4 vt0 = tc0[tid];
    float4 vt1 = tc1[tid];
    float4 vi0 = ic0[tid];
    float4 vi1 = ic1[tid];

    float acc[NACC];
    // 0: |img_b|^2   1: |txt_b|^2   2: dot(img_b, txt_b)
    // 3: dot(img_b, txt_c0)  4: |txt_c0|^2
    // 5: dot(img_b, txt_c1)  6: |txt_c1|^2
    // 7: dot(txt_b, img_e0)  8: |img_e0|^2
    // 9: dot(txt_b, img_e1) 10: |img_e1|^2
    acc[0]  = vi.x*vi.x  + vi.y*vi.y  + vi.z*vi.z  + vi.w*vi.w;
    acc[1]  = vt.x*vt.x  + vt.y*vt.y  + vt.z*vt.z  + vt.w*vt.w;
    acc[2]  = vi.x*vt.x  + vi.y*vt.y  + vi.z*vt.z  + vi.w*vt.w;
    acc[3]  = vi.x*vt0.x + vi.y*vt0.y + vi.z*vt0.z + vi.w*vt0.w;
    acc[4]  = vt0.x*vt0.x+ vt0.y*vt0.y+ vt0.z*vt0.z+ vt0.w*vt0.w;
    acc[5]  = vi.x*vt1.x + vi.y*vt1.y + vi.z*vt1.z + vi.w*vt1.w;
    acc[6]  = vt1.x*vt1.x+ vt1.y*vt1.y+ vt1.z*vt1.z+ vt1.w*vt1.w;
    acc[7]  = vt.x*vi0.x + vt.y*vi0.y + vt.z*vi0.z + vt.w*vi0.w;
    acc[8]  = vi0.x*vi0.x+ vi0.y*vi0.y+ vi0.z*vi0.z+ vi0.w*vi0.w;
    acc[9]  = vt.x*vi1.x + vt.y*vi1.y + vt.z*vi1.z + vt.w*vi1.w;
    acc[10] = vi1.x*vi1.x+ vi1.y*vi1.y+ vi1.z*vi1.z+ vi1.w*vi1.w;

    __shared__ float smem[(THREADS / 32) * NACC];
    block_reduce_11(acc, smem, tid);

    if (tid == 0) {
        const float ni  = sqrtf(acc[0]);   // |img_b|
        const float nt  = sqrtf(acc[1]);   // |txt_b|
        const float nprod = ni * nt;

        // cosine sim (unclamped) and positive distance (clamped denom)
        const float sim = acc[2] / nprod;
        const float pos_dist = 1.0f - acc[2] / fmaxf(nprod, EPSF);

        // i2t negatives: anchor img_b vs txt candidates
        const float dT0 = 1.0f - acc[3] / fmaxf(ni * sqrtf(acc[4]), EPSF);
        const float dT1 = 1.0f - acc[5] / fmaxf(ni * sqrtf(acc[6]), EPSF);
        const float i2t_neg = fminf(dT0, dT1);  // d1<=d0 picks d1; ties equal

        // t2i negatives: anchor txt_b vs img candidates
        const float dI0 = 1.0f - acc[7] / fmaxf(nt * sqrtf(acc[8]),  EPSF);
        const float dI1 = 1.0f - acc[9] / fmaxf(nt * sqrtf(acc[10]), EPSF);
        const float t2i_neg = fminf(dI0, dI1);

        const float i2t_trip = fmaxf(pos_dist - i2t_neg + MARGIN, 0.0f);
        const float t2i_trip = fmaxf(pos_dist - t2i_neg + MARGIN, 0.0f);

        // outputs: [loss, i2t_cosine(B), t2i_cosine(B)]
        out[1 + b]      = sim;
        out[1 + BB + b] = sim;  // t2i_cosine == i2t_cosine (symmetric pair)
        atomicAdd(out, (i2t_trip + t2i_trip) * (1.0f / (float)BB));
    }
}

extern "C" void kernel_launch(void* const* d_in, const int* in_sizes, int n_in,
                              void* d_out, int out_size) {
    const float* img      = (const float*)d_in[0];
    const float* txt      = (const float*)d_in[1];
    // d_in[2] = labels (unused: anchor ids are identity), d_in[3] = locations (unused)
    const int*   cand_img = (const int*)d_in[4];
    const int*   cand_txt = (const int*)d_in[5];
    float* out = (float*)d_out;

    init_out_kernel<<<1, 1>>>(out);
    contrastive_kernel<<<BB, THREADS>>>(img, txt, cand_img, cand_txt, out);
}

// round 3
// speedup vs baseline: 1.3263x; 1.3263x over previous
#include <cuda_runtime.h>

#define BB 4096
#define DD 1024
#define THREADS 256
#define WARPS_PER_BLOCK (THREADS / 32)
#define NBLOCKS (BB / WARPS_PER_BLOCK)
#define CHUNKS (DD / 4 / 32)   // 8 float4 chunks per lane per row
#define EPSF 1e-8f
#define MARGIN 0.2f
#define NACC 11

__global__ void init_out_kernel(float* out) {
    out[0] = 0.0f;
}

__global__ __launch_bounds__(THREADS, 2)   // allow up to 128 regs: keep loads batched
void contrastive_kernel(const float* __restrict__ img,
                        const float* __restrict__ txt,
                        const int* __restrict__ cand_img,
                        const int* __restrict__ cand_txt,
                        float* __restrict__ out) {
    const int tid  = threadIdx.x;
    const int warp = tid >> 5;
    const int lane = tid & 31;
    const int b    = blockIdx.x * WARPS_PER_BLOCK + warp;   // one warp per row

    // candidate indices (converged scalar loads broadcast in L1)
    const int ct0 = cand_txt[2 * b + 0];
    const int ct1 = cand_txt[2 * b + 1];
    const int ci0 = cand_img[2 * b + 0];
    const int ci1 = cand_img[2 * b + 1];

    const float4* ib  = (const float4*)(img + (size_t)b   * DD);
    const float4* tb  = (const float4*)(txt + (size_t)b   * DD);
    const float4* tc0 = (const float4*)(txt + (size_t)ct0 * DD);
    const float4* tc1 = (const float4*)(txt + (size_t)ct1 * DD);
    const float4* ic0 = (const float4*)(img + (size_t)ci0 * DD);
    const float4* ic1 = (const float4*)(img + (size_t)ci1 * DD);

    // 0: |img_b|^2   1: |txt_b|^2   2: dot(img_b, txt_b)
    // 3: dot(img_b, txt_c0)  4: |txt_c0|^2
    // 5: dot(img_b, txt_c1)  6: |txt_c1|^2
    // 7: dot(txt_b, img_e0)  8: |img_e0|^2
    // 9: dot(txt_b, img_e1) 10: |img_e1|^2
    float acc[NACC];
    #pragma unroll
    for (int a = 0; a < NACC; a++) acc[a] = 0.0f;

    #pragma unroll
    for (int c = 0; c < CHUNKS; c++) {
        const int o = c * 32 + lane;
        float4 vi  = ib[o];
        float4 vt  = tb[o];
        float4 vt0 = tc0[o];
        float4 vt1 = tc1[o];
        float4 vi0 = ic0[o];
        float4 vi1 = ic1[o];

        acc[0]  += vi.x*vi.x  + vi.y*vi.y  + vi.z*vi.z  + vi.w*vi.w;
        acc[1]  += vt.x*vt.x  + vt.y*vt.y  + vt.z*vt.z  + vt.w*vt.w;
        acc[2]  += vi.x*vt.x  + vi.y*vt.y  + vi.z*vt.z  + vi.w*vt.w;
        acc[3]  += vi.x*vt0.x + vi.y*vt0.y + vi.z*vt0.z + vi.w*vt0.w;
        acc[4]  += vt0.x*vt0.x+ vt0.y*vt0.y+ vt0.z*vt0.z+ vt0.w*vt0.w;
        acc[5]  += vi.x*vt1.x + vi.y*vt1.y + vi.z*vt1.z + vi.w*vt1.w;
        acc[6]  += vt1.x*vt1.x+ vt1.y*vt1.y+ vt1.z*vt1.z+ vt1.w*vt1.w;
        acc[7]  += vt.x*vi0.x + vt.y*vi0.y + vt.z*vi0.z + vt.w*vi0.w;
        acc[8]  += vi0.x*vi0.x+ vi0.y*vi0.y+ vi0.z*vi0.z+ vi0.w*vi0.w;
        acc[9]  += vt.x*vi1.x + vt.y*vi1.y + vt.z*vi1.z + vt.w*vi1.w;
        acc[10] += vi1.x*vi1.x+ vi1.y*vi1.y+ vi1.z*vi1.z+ vi1.w*vi1.w;
    }

    // single warp-level reduction per ROW (was: per block of 8 warps)
    #pragma unroll
    for (int a = 0; a < NACC; a++) {
        float x = acc[a];
        #pragma unroll
        for (int off = 16; off > 0; off >>= 1)
            x += __shfl_xor_sync(0xFFFFFFFFu, x, off);
        acc[a] = x;
    }

    __shared__ float sloss[WARPS_PER_BLOCK];

    if (lane == 0) {
        const float ni    = sqrtf(acc[0]);   // |img_b|
        const float nt    = sqrtf(acc[1]);   // |txt_b|
        const float nprod = ni * nt;

        const float sim      = acc[2] / nprod;                      // unclamped
        const float pos_dist = 1.0f - acc[2] / fmaxf(nprod, EPSF);  // clamped

        const float dT0 = 1.0f - acc[3] / fmaxf(ni * sqrtf(acc[4]), EPSF);
        const float dT1 = 1.0f - acc[5] / fmaxf(ni * sqrtf(acc[6]), EPSF);
        const float i2t_neg = fminf(dT0, dT1);   // `d1<=d0` tie-break == min

        const float dI0 = 1.0f - acc[7] / fmaxf(nt * sqrtf(acc[8]),  EPSF);
        const float dI1 = 1.0f - acc[9] / fmaxf(nt * sqrtf(acc[10]), EPSF);
        const float t2i_neg = fminf(dI0, dI1);

        const float i2t_trip = fmaxf(pos_dist - i2t_neg + MARGIN, 0.0f);
        const float t2i_trip = fmaxf(pos_dist - t2i_neg + MARGIN, 0.0f);

        // outputs: [loss, i2t_cosine(B), t2i_cosine(B)]; cosines identical pair
        out[1 + b]      = sim;
        out[1 + BB + b] = sim;
        sloss[warp] = (i2t_trip + t2i_trip) * (1.0f / (float)BB);
    }

    __syncthreads();
    if (tid == 0) {
        float s = 0.0f;
        #pragma unroll
        for (int w = 0; w < WARPS_PER_BLOCK; w++) s += sloss[w];
        atomicAdd(out, s);   // 512 same-address atomics total
    }
}

extern "C" void kernel_launch(void* const* d_in, const int* in_sizes, int n_in,
                              void* d_out, int out_size) {
    const float* img      = (const float*)d_in[0];
    const float* txt      = (const float*)d_in[1];
    // d_in[2] = labels (identity anchors, unused), d_in[3] = locations (unused)
    const int*   cand_img = (const int*)d_in[4];
    const int*   cand_txt = (const int*)d_in[5];
    float* out = (float*)d_out;

    init_out_kernel<<<1, 1>>>(out);
    contrastive_kernel<<<NBLOCKS, THREADS>>>(img, txt, cand_img, cand_txt, out);
}

// round 5
// speedup vs baseline: 1.5689x; 1.1830x over previous
#include <cuda_runtime.h>

#define BB 4096
#define DD 1024
#define THREADS 256
#define WARPS_PER_BLOCK (THREADS / 32)
#define NBLOCKS (BB / WARPS_PER_BLOCK)
#define CHUNKS (DD / 4 / 32)   // 8 float4 chunks per lane per row
#define EPSF 1e-8f
#define MARGIN 0.2f
#define NACC 11

__global__ void init_out_kernel(float* out) {
    out[0] = 0.0f;
}

__global__ __launch_bounds__(THREADS, 4)   // 64-reg budget: 4 blocks/SM, single wave,
                                           // still room for 6 in-flight float4 loads
void contrastive_kernel(const float* __restrict__ img,
                        const float* __restrict__ txt,
                        const int* __restrict__ cand_img,
                        const int* __restrict__ cand_txt,
                        float* __restrict__ out) {
    const int tid  = threadIdx.x;
    const int warp = tid >> 5;
    const int lane = tid & 31;
    const int b    = blockIdx.x * WARPS_PER_BLOCK + warp;   // one warp per row

    // candidate indices (converged scalar loads broadcast in L1)
    const int ct0 = cand_txt[2 * b + 0];
    const int ct1 = cand_txt[2 * b + 1];
    const int ci0 = cand_img[2 * b + 0];
    const int ci1 = cand_img[2 * b + 1];

    const float4* ib  = (const float4*)(img + (size_t)b   * DD);
    const float4* tb  = (const float4*)(txt + (size_t)b   * DD);
    const float4* tc0 = (const float4*)(txt + (size_t)ct0 * DD);
    const float4* tc1 = (const float4*)(txt + (size_t)ct1 * DD);
    const float4* ic0 = (const float4*)(img + (size_t)ci0 * DD);
    const float4* ic1 = (const float4*)(img + (size_t)ci1 * DD);

    // 0: |img_b|^2   1: |txt_b|^2   2: dot(img_b, txt_b)
    // 3: dot(img_b, txt_c0)  4: |txt_c0|^2
    // 5: dot(img_b, txt_c1)  6: |txt_c1|^2
    // 7: dot(txt_b, img_e0)  8: |img_e0|^2
    // 9: dot(txt_b, img_e1) 10: |img_e1|^2
    float acc[NACC];
    #pragma unroll
    for (int a = 0; a < NACC; a++) acc[a] = 0.0f;

    #pragma unroll
    for (int c = 0; c < CHUNKS; c++) {
        const int o = c * 32 + lane;
        float4 vi  = ib[o];
        float4 vt  = tb[o];
        float4 vt0 = tc0[o];
        float4 vt1 = tc1[o];
        float4 vi0 = ic0[o];
        float4 vi1 = ic1[o];

        acc[0]  += vi.x*vi.x  + vi.y*vi.y  + vi.z*vi.z  + vi.w*vi.w;
        acc[1]  += vt.x*vt.x  + vt.y*vt.y  + vt.z*vt.z  + vt.w*vt.w;
        acc[2]  += vi.x*vt.x  + vi.y*vt.y  + vi.z*vt.z  + vi.w*vt.w;
        acc[3]  += vi.x*vt0.x + vi.y*vt0.y + vi.z*vt0.z + vi.w*vt0.w;
        acc[4]  += vt0.x*vt0.x+ vt0.y*vt0.y+ vt0.z*vt0.z+ vt0.w*vt0.w;
        acc[5]  += vi.x*vt1.x + vi.y*vt1.y + vi.z*vt1.z + vi.w*vt1.w;
        acc[6]  += vt1.x*vt1.x+ vt1.y*vt1.y+ vt1.z*vt1.z+ vt1.w*vt1.w;
        acc[7]  += vt.x*vi0.x + vt.y*vi0.y + vt.z*vi0.z + vt.w*vi0.w;
        acc[8]  += vi0.x*vi0.x+ vi0.y*vi0.y+ vi0.z*vi0.z+ vi0.w*vi0.w;
        acc[9]  += vt.x*vi1.x + vt.y*vi1.y + vt.z*vi1.z + vt.w*vi1.w;
        acc[10] += vi1.x*vi1.x+ vi1.y*vi1.y+ vi1.z*vi1.z+ vi1.w*vi1.w;
    }

    // single warp-level reduction per row
    #pragma unroll
    for (int a = 0; a < NACC; a++) {
        float x = acc[a];
        #pragma unroll
        for (int off = 16; off > 0; off >>= 1)
            x += __shfl_xor_sync(0xFFFFFFFFu, x, off);
        acc[a] = x;
    }

    __shared__ float sloss[WARPS_PER_BLOCK];

    if (lane == 0) {
        const float ni    = sqrtf(acc[0]);   // |img_b|
        const float nt    = sqrtf(acc[1]);   // |txt_b|
        const float nprod = ni * nt;

        const float sim      = acc[2] / nprod;                      // unclamped
        const float pos_dist = 1.0f - acc[2] / fmaxf(nprod, EPSF);  // clamped

        const float dT0 = 1.0f - acc[3] / fmaxf(ni * sqrtf(acc[4]), EPSF);
        const float dT1 = 1.0f - acc[5] / fmaxf(ni * sqrtf(acc[6]), EPSF);
        const float i2t_neg = fminf(dT0, dT1);   // `d1<=d0` tie-break == min

        const float dI0 = 1.0f - acc[7] / fmaxf(nt * sqrtf(acc[8]),  EPSF);
        const float dI1 = 1.0f - acc[9] / fmaxf(nt * sqrtf(acc[10]), EPSF);
        const float t2i_neg = fminf(dI0, dI1);

        const float i2t_trip = fmaxf(pos_dist - i2t_neg + MARGIN, 0.0f);
        const float t2i_trip = fmaxf(pos_dist - t2i_neg + MARGIN, 0.0f);

        // outputs: [loss, i2t_cosine(B), t2i_cosine(B)]; cosines identical pair
        out[1 + b]      = sim;
        out[1 + BB + b] = sim;
        sloss[warp] = (i2t_trip + t2i_trip) * (1.0f / (float)BB);
    }

    __syncthreads();
    if (tid == 0) {
        float s = 0.0f;
        #pragma unroll
        for (int w = 0; w < WARPS_PER_BLOCK; w++) s += sloss[w];
        atomicAdd(out, s);   // 512 same-address atomics total
    }
}

extern "C" void kernel_launch(void* const* d_in, const int* in_sizes, int n_in,
                              void* d_out, int out_size) {
    const float* img      = (const float*)d_in[0];
    const float* txt      = (const float*)d_in[1];
    // d_in[2] = labels (identity anchors, unused), d_in[3] = locations (unused)
    const int*   cand_img = (const int*)d_in[4];
    const int*   cand_txt = (const int*)d_in[5];
    float* out = (float*)d_out;

    init_out_kernel<<<1, 1>>>(out);
    contrastive_kernel<<<NBLOCKS, THREADS>>>(img, txt, cand_img, cand_txt, out);
}